// round 4
// baseline (speedup 1.0000x reference)
#include <cuda_runtime.h>

// SpatialTransformer: 3D trilinear warp, smem tile with conflict-free lane map.
// vol: [B=2, 160, 192, 160, 1] f32 ; trf: [..., 3] f32 ; out like vol.
//
// Block = 16x16x16 output tile, 256 threads. Smem tile layout [x][y][z]:
// 22 x 22 x 24 floats (halo 3 in x/y, z covers [z0-4, z0+19]), z contiguous,
// x-stride 528 === 16 (mod 32). Warp lanes = 16 consecutive z x 2 consecutive
// x -> bank = 16*xi + zi: perfect permutation; displacement jitter only adds
// sparse degree-2 conflicts. Each warp owns one y (and y+8); 8 x-pair iters,
// 2 voxels per iteration for ILP. Out-of-tile corners (~0.5%) take an exact
// global fallback identical to the reference math.

#define DX 160
#define DY 192
#define DZ 160
#define NB 2
#define TS 16
#define SX 22
#define SY 22
#define SZ 24
#define XSTRIDE (SY*SZ)        // 528
#define SELEMS (SX*SY*SZ)      // 11616 floats = 46464 B

extern __shared__ float tile[];

__device__ __forceinline__ int iclamp(int v, int hi) {
    return min(max(v, 0), hi);
}

struct Corner8 { float v000,v001,v010,v011,v100,v101,v110,v111; };

__device__ __forceinline__ float interp_one(
    const float* __restrict__ v, const float* __restrict__ trf3,
    int gx, int gy, int gz, int xlo, int ylo, int zlo)
{
    float tx = __ldg(trf3 + 0);
    float ty = __ldg(trf3 + 1);
    float tz = __ldg(trf3 + 2);

    float lx = fminf(fmaxf((float)gx + tx, 0.0f), (float)(DX - 1));
    float ly = fminf(fmaxf((float)gy + ty, 0.0f), (float)(DY - 1));
    float lz = fminf(fmaxf((float)gz + tz, 0.0f), (float)(DZ - 1));

    int ix0 = (int)floorf(lx);
    int iy0 = (int)floorf(ly);
    int iz0 = (int)floorf(lz);
    int ix1 = min(ix0 + 1, DX - 1);
    int iy1 = min(iy0 + 1, DY - 1);
    int iz1 = min(iz0 + 1, DZ - 1);

    float wx1 = (float)ix1 - lx;   // lower-corner weight (d1)
    float wy1 = (float)iy1 - ly;
    float wz1 = (float)iz1 - lz;
    float wx0 = 1.0f - wx1;
    float wy0 = 1.0f - wy1;
    float wz0 = 1.0f - wz1;

    Corner8 c;
    unsigned sux = (unsigned)(ix0 - xlo);
    unsigned suy = (unsigned)(iy0 - ylo);
    unsigned suz = (unsigned)(iz0 - zlo);

    if (sux <= (unsigned)(SX - 2) &&
        suy <= (unsigned)(SY - 2) &&
        suz <= (unsigned)(SZ - 2)) {
        const float* t00 = &tile[(int)sux * XSTRIDE + (int)suy * SZ + (int)suz];
        int sxs = (ix1 - ix0) * XSTRIDE;
        int sys = (iy1 - iy0) * SZ;
        int szs = iz1 - iz0;
        c.v000 = t00[0];         c.v001 = t00[szs];
        c.v010 = t00[sys];       c.v011 = t00[sys + szs];
        c.v100 = t00[sxs];       c.v101 = t00[sxs + szs];
        c.v110 = t00[sxs + sys]; c.v111 = t00[sxs + sys + szs];
    } else {
        const float* p00 = v + ((size_t)ix0 * DY + iy0) * DZ;
        const float* p01 = v + ((size_t)ix0 * DY + iy1) * DZ;
        const float* p10 = v + ((size_t)ix1 * DY + iy0) * DZ;
        const float* p11 = v + ((size_t)ix1 * DY + iy1) * DZ;
        c.v000 = __ldg(p00 + iz0); c.v001 = __ldg(p00 + iz1);
        c.v010 = __ldg(p01 + iz0); c.v011 = __ldg(p01 + iz1);
        c.v100 = __ldg(p10 + iz0); c.v101 = __ldg(p10 + iz1);
        c.v110 = __ldg(p11 + iz0); c.v111 = __ldg(p11 + iz1);
    }

    float c00 = c.v000 * wz1 + c.v001 * wz0;
    float c01 = c.v010 * wz1 + c.v011 * wz0;
    float c10 = c.v100 * wz1 + c.v101 * wz0;
    float c11 = c.v110 * wz1 + c.v111 * wz0;
    float c0  = c00 * wy1 + c01 * wy0;
    float c1  = c10 * wy1 + c11 * wy0;
    return c0 * wx1 + c1 * wx0;
}

__global__ __launch_bounds__(256, 4)
void warp_tile3_kernel(const float* __restrict__ vol,
                       const float* __restrict__ trf,
                       float* __restrict__ out)
{
    const int tid = threadIdx.x;
    const int b  = blockIdx.z / (DX / TS);
    const int x0 = (blockIdx.z % (DX / TS)) * TS;
    const int y0 = blockIdx.y * TS;
    const int z0 = blockIdx.x * TS;

    const float* __restrict__ v = vol + (size_t)b * (DX * DY * DZ);
    const int xlo = x0 - 3, ylo = y0 - 3, zlo = z0 - 4;

    // ---------------- cooperative tile load ----------------
    if (zlo >= 0 && z0 + 19 <= DZ - 1) {
        // z-interior: 24 z values = 6 aligned float4 per (x,y) row
        for (int idx = tid; idx < SX * SY * 6; idx += 256) {
            int c   = idx % 6;
            int row = idx / 6;
            int py  = row % SY;
            int px  = row / SY;
            int gx  = iclamp(xlo + px, DX - 1);
            int gy  = iclamp(ylo + py, DY - 1);
            float4 val = __ldg(reinterpret_cast<const float4*>(
                                   v + ((size_t)gx * DY + gy) * DZ + zlo) + c);
            *reinterpret_cast<float4*>(&tile[(px * SY + py) * SZ + c * 4]) = val;
        }
    } else {
        for (int idx = tid; idx < SELEMS; idx += 256) {
            int pz = idx % SZ;
            int r  = idx / SZ;
            int py = r % SY;
            int px = r / SY;
            int gx = iclamp(xlo + px, DX - 1);
            int gy = iclamp(ylo + py, DY - 1);
            int gz = iclamp(zlo + pz, DZ - 1);
            tile[idx] = __ldg(v + ((size_t)gx * DY + gy) * DZ + gz);
        }
    }
    __syncthreads();

    // ---------------- per-voxel warp ----------------
    const int w    = tid >> 5;         // warp id 0..7 -> y offset
    const int lane = tid & 31;
    const int zi   = lane & 15;        // 16 consecutive z
    const int xi   = lane >> 4;        // 2 consecutive x

    const int gz  = z0 + zi;
    const int gy0 = y0 + w;            // chain A
    const int gy1 = y0 + w + 8;        // chain B

#pragma unroll 1
    for (int xp = 0; xp < 8; ++xp) {
        const int gx = x0 + xp * 2 + xi;
        const size_t rowA = (((size_t)b * DX + gx) * DY + gy0) * DZ + gz;
        const size_t rowB = rowA + (size_t)8 * DZ;

        float ra = interp_one(v, trf + rowA * 3, gx, gy0, gz, xlo, ylo, zlo);
        float rb = interp_one(v, trf + rowB * 3, gx, gy1, gz, xlo, ylo, zlo);

        out[rowA] = ra;
        out[rowB] = rb;
    }
}

extern "C" void kernel_launch(void* const* d_in, const int* in_sizes, int n_in,
                              void* d_out, int out_size)
{
    const float* vol = (const float*)d_in[0];
    const float* trf = (const float*)d_in[1];
    float* out = (float*)d_out;

    cudaFuncSetAttribute(warp_tile3_kernel,
                         cudaFuncAttributeMaxDynamicSharedMemorySize,
                         SELEMS * (int)sizeof(float));

    dim3 grid(DZ / TS, DY / TS, NB * (DX / TS));  // (10, 12, 20)
    warp_tile3_kernel<<<grid, 256, SELEMS * sizeof(float)>>>(vol, trf, out);
}